// round 1
// baseline (speedup 1.0000x reference)
#include <cuda_runtime.h>

// Problem constants
#define NB   32      // batch
#define NIN  2048    // input capsules
#define NOUT 64      // output capsules
#define DD   16      // capsule dim
#define ROW  1024    // NOUT*DD floats per (b,i) row
#define WPB  64      // warps per batch item
#define IPW  32      // input rows per warp (NIN / WPB)

// Scratch (no allocation allowed): deterministic per-warp partial sums + routing weight vector
__device__ float g_partials[NB * WPB * ROW];  // 8 MB
__device__ float g_ow[NB * ROW];              // out0 (pass2) or out0+out1 (pass3)

// ---------------------------------------------------------------------------
// Pass kernel: one warp processes IPW contiguous rows of x[b, i, :, :].
// For each row: p_j = dot(x[j,:], ow[j,:]); a = softmax_j(p); acc += a_j * x[j,:].
// uniform=1 (round 0): a = 1/64 exactly (softmax of zero priors), skip dot/softmax.
// Lane mapping: float4 index f = lane + 32*k (k=0..7) -> j = (lane>>2) + 8k, d = (lane&3)*4.
// ---------------------------------------------------------------------------
__global__ void __launch_bounds__(256, 2)
route_pass(const float* __restrict__ x, int uniform)
{
    const int b    = blockIdx.x >> 3;
    const int wb   = ((blockIdx.x & 7) << 3) | (threadIdx.x >> 5);  // warp id within b: 0..63
    const int lane = threadIdx.x & 31;

    // Per-thread slice of the routing weight vector (fixed across all rows)
    float4 w[8];
    if (!uniform) {
        const float4* owp = reinterpret_cast<const float4*>(g_ow) + (size_t)b * (ROW / 4);
#pragma unroll
        for (int k = 0; k < 8; k++) w[k] = owp[lane + 32 * k];
    }

    float4 acc[8];
#pragma unroll
    for (int k = 0; k < 8; k++) acc[k] = make_float4(0.f, 0.f, 0.f, 0.f);

    const float4* base = reinterpret_cast<const float4*>(x)
        + ((size_t)b * NIN + (size_t)wb * IPW) * (ROW / 4);

    for (int ii = 0; ii < IPW; ii++) {
        const float4* rowp = base + (size_t)ii * (ROW / 4);
        float4 xv[8];
#pragma unroll
        for (int k = 0; k < 8; k++) xv[k] = __ldcs(rowp + lane + 32 * k);  // streaming: keep out of L2

        float a[8];
        if (uniform) {
#pragma unroll
            for (int k = 0; k < 8; k++) a[k] = 0.015625f;  // 1/64 exact
        } else {
            float p[8];
#pragma unroll
            for (int k = 0; k < 8; k++) {
                float t = xv[k].x * w[k].x + xv[k].y * w[k].y
                        + xv[k].z * w[k].z + xv[k].w * w[k].w;
                // full dot over d=16: reduce across the 4 lanes sharing j
                t += __shfl_xor_sync(0xffffffffu, t, 1);
                t += __shfl_xor_sync(0xffffffffu, t, 2);
                p[k] = t;  // replicated within 4-lane group
            }
            // softmax over all 64 j (8 per lane-group x 8 groups)
            float m = p[0];
#pragma unroll
            for (int k = 1; k < 8; k++) m = fmaxf(m, p[k]);
            m = fmaxf(m, __shfl_xor_sync(0xffffffffu, m, 4));
            m = fmaxf(m, __shfl_xor_sync(0xffffffffu, m, 8));
            m = fmaxf(m, __shfl_xor_sync(0xffffffffu, m, 16));
            float s = 0.f;
#pragma unroll
            for (int k = 0; k < 8; k++) { a[k] = __expf(p[k] - m); s += a[k]; }
            s += __shfl_xor_sync(0xffffffffu, s, 4);
            s += __shfl_xor_sync(0xffffffffu, s, 8);
            s += __shfl_xor_sync(0xffffffffu, s, 16);
            float inv = 1.0f / s;
#pragma unroll
            for (int k = 0; k < 8; k++) a[k] *= inv;
        }
#pragma unroll
        for (int k = 0; k < 8; k++) {
            acc[k].x = fmaf(a[k], xv[k].x, acc[k].x);
            acc[k].y = fmaf(a[k], xv[k].y, acc[k].y);
            acc[k].z = fmaf(a[k], xv[k].z, acc[k].z);
            acc[k].w = fmaf(a[k], xv[k].w, acc[k].w);
        }
    }

    float4* pp = reinterpret_cast<float4*>(g_partials)
        + ((size_t)(b * WPB + wb)) * (ROW / 4);
#pragma unroll
    for (int k = 0; k < 8; k++) pp[lane + 32 * k] = acc[k];
}

// ---------------------------------------------------------------------------
// Reduce partials (deterministic fixed order), add bias, squash per (b,j).
// ow_mode: 0=none, 1=set g_ow=out, 2=g_ow+=out. final_out: write d_out.
// ---------------------------------------------------------------------------
__global__ void __launch_bounds__(256)
reduce_squash(const float* __restrict__ bias, float* __restrict__ dout,
              int ow_mode, int final_out)
{
    const int b = blockIdx.x;
    const int t = threadIdx.x;  // t covers 1024 floats as 256 float4; j = t>>2

    const float4* pp = reinterpret_cast<const float4*>(g_partials)
        + (size_t)b * WPB * (ROW / 4);
    float4 s = make_float4(0.f, 0.f, 0.f, 0.f);
#pragma unroll 8
    for (int w2 = 0; w2 < WPB; w2++) {
        float4 v = pp[w2 * (ROW / 4) + t];
        s.x += v.x; s.y += v.y; s.z += v.z; s.w += v.w;
    }
    float4 bb = reinterpret_cast<const float4*>(bias)[t];
    s.x += bb.x; s.y += bb.y; s.z += bb.z; s.w += bb.w;

    // squash over d=16: norm^2 across the 4 threads sharing j
    float n2 = s.x * s.x + s.y * s.y + s.z * s.z + s.w * s.w;
    n2 += __shfl_xor_sync(0xffffffffu, n2, 1);
    n2 += __shfl_xor_sync(0xffffffffu, n2, 2);
    float scale = n2 / ((1.0f + n2) * sqrtf(n2 + 1e-7f));

    float4 o = make_float4(s.x * scale, s.y * scale, s.z * scale, s.w * scale);

    if (final_out) {
        reinterpret_cast<float4*>(dout)[b * (ROW / 4) + t] = o;
    }
    if (ow_mode == 1) {
        reinterpret_cast<float4*>(g_ow)[b * (ROW / 4) + t] = o;
    } else if (ow_mode == 2) {
        float4 c = reinterpret_cast<const float4*>(g_ow)[b * (ROW / 4) + t];
        c.x += o.x; c.y += o.y; c.z += o.z; c.w += o.w;
        reinterpret_cast<float4*>(g_ow)[b * (ROW / 4) + t] = c;
    }
}

extern "C" void kernel_launch(void* const* d_in, const int* in_sizes, int n_in,
                              void* d_out, int out_size)
{
    const float* x    = (const float*)d_in[0];   // [32, 2048, 64, 16]
    const float* bias = (const float*)d_in[1];   // [64, 16]
    float* out = (float*)d_out;                  // [32, 64, 16]

    (void)in_sizes; (void)n_in; (void)out_size;

    dim3 gp(NB * 8), bp(256);
    dim3 gr(NB), br(256);

    // Round 0: uniform weights (softmax of zero priors = 1/64)
    route_pass<<<gp, bp>>>(x, 1);
    reduce_squash<<<gr, br>>>(bias, out, /*ow_mode=*/1, /*final=*/0);  // g_ow = out0

    // Round 1: weights from softmax(dot(x, out0))
    route_pass<<<gp, bp>>>(x, 0);
    reduce_squash<<<gr, br>>>(bias, out, /*ow_mode=*/2, /*final=*/0);  // g_ow = out0+out1

    // Round 2: weights from softmax(dot(x, out0+out1)) -- linearity of priors
    route_pass<<<gp, bp>>>(x, 0);
    reduce_squash<<<gr, br>>>(bias, out, /*ow_mode=*/0, /*final=*/1);
}

// round 2
// speedup vs baseline: 1.1179x; 1.1179x over previous
#include <cuda_runtime.h>

// Problem constants
#define NB   32      // batch
#define NIN  2048    // input capsules
#define NOUT 64      // output capsules
#define DD   16      // capsule dim
#define ROW  1024    // NOUT*DD floats per (b,i) row
#define SLICES 8     // blocks per batch item
#define WPBLK  8     // warps per block
#define IPW  32      // input rows per warp (NIN / (SLICES*WPBLK))

// Scratch (no allocation allowed): per-BLOCK partial sums + routing weight vector
__device__ float g_partials[NB * SLICES * ROW];  // 1 MB (stays in L2)
__device__ float g_ow[NB * ROW];                 // out0 (pass2) or out0+out1 (pass3)

// ---------------------------------------------------------------------------
// Pass kernel: one warp processes IPW contiguous rows of x[b, i, :, :].
// For each row: p_j = dot(x[j,:], ow[j,:]); a = softmax_j(p); acc += a_j * x[j,:].
// uniform=1 (round 0): a = 1/64 exactly (softmax of zero priors).
// Lane mapping: float4 index f = lane + 32*k (k=0..7) -> j = (lane>>2) + 8k, d = (lane&3)*4.
// Tail: the 8 warps reduce through shared memory -> ONE partial per block.
// ---------------------------------------------------------------------------
__global__ void __launch_bounds__(256, 2)
route_pass(const float* __restrict__ x, int uniform)
{
    const int b     = blockIdx.x >> 3;
    const int slice = blockIdx.x & 7;
    const int wloc  = threadIdx.x >> 5;            // warp in block: 0..7
    const int wb    = (slice << 3) | wloc;         // warp id within b: 0..63
    const int lane  = threadIdx.x & 31;

    // Per-thread slice of the routing weight vector (fixed across all rows)
    float4 w[8];
    if (!uniform) {
        const float4* owp = reinterpret_cast<const float4*>(g_ow) + (size_t)b * (ROW / 4);
#pragma unroll
        for (int k = 0; k < 8; k++) w[k] = owp[lane + 32 * k];
    }

    float4 acc[8];
#pragma unroll
    for (int k = 0; k < 8; k++) acc[k] = make_float4(0.f, 0.f, 0.f, 0.f);

    const float4* base = reinterpret_cast<const float4*>(x)
        + ((size_t)b * NIN + (size_t)wb * IPW) * (ROW / 4);

    for (int ii = 0; ii < IPW; ii++) {
        const float4* rowp = base + (size_t)ii * (ROW / 4);
        float4 xv[8];
#pragma unroll
        for (int k = 0; k < 8; k++) xv[k] = __ldcs(rowp + lane + 32 * k);  // streaming

        float a[8];
        if (uniform) {
#pragma unroll
            for (int k = 0; k < 8; k++) a[k] = 0.015625f;  // 1/64 exact
        } else {
            float p[8];
#pragma unroll
            for (int k = 0; k < 8; k++) {
                float t = xv[k].x * w[k].x + xv[k].y * w[k].y
                        + xv[k].z * w[k].z + xv[k].w * w[k].w;
                t += __shfl_xor_sync(0xffffffffu, t, 1);
                t += __shfl_xor_sync(0xffffffffu, t, 2);
                p[k] = t;  // dot over d=16, replicated within 4-lane group
            }
            // softmax over all 64 j
            float m = p[0];
#pragma unroll
            for (int k = 1; k < 8; k++) m = fmaxf(m, p[k]);
            m = fmaxf(m, __shfl_xor_sync(0xffffffffu, m, 4));
            m = fmaxf(m, __shfl_xor_sync(0xffffffffu, m, 8));
            m = fmaxf(m, __shfl_xor_sync(0xffffffffu, m, 16));
            float s = 0.f;
#pragma unroll
            for (int k = 0; k < 8; k++) { a[k] = __expf(p[k] - m); s += a[k]; }
            s += __shfl_xor_sync(0xffffffffu, s, 4);
            s += __shfl_xor_sync(0xffffffffu, s, 8);
            s += __shfl_xor_sync(0xffffffffu, s, 16);
            float inv = 1.0f / s;
#pragma unroll
            for (int k = 0; k < 8; k++) a[k] *= inv;
        }
#pragma unroll
        for (int k = 0; k < 8; k++) {
            acc[k].x = fmaf(a[k], xv[k].x, acc[k].x);
            acc[k].y = fmaf(a[k], xv[k].y, acc[k].y);
            acc[k].z = fmaf(a[k], xv[k].z, acc[k].z);
            acc[k].w = fmaf(a[k], xv[k].w, acc[k].w);
        }
    }

    // ---- in-block reduction: 8 warp-accumulators -> 1 partial (deterministic order)
    __shared__ float4 sbuf[WPBLK * 256];   // 32 KB
#pragma unroll
    for (int k = 0; k < 8; k++) sbuf[wloc * 256 + lane + 32 * k] = acc[k];
    __syncthreads();

    const int t = threadIdx.x;
    float4 s = make_float4(0.f, 0.f, 0.f, 0.f);
#pragma unroll
    for (int w2 = 0; w2 < WPBLK; w2++) {
        float4 v = sbuf[w2 * 256 + t];
        s.x += v.x; s.y += v.y; s.z += v.z; s.w += v.w;
    }
    reinterpret_cast<float4*>(g_partials)[((size_t)b * SLICES + slice) * 256 + t] = s;
}

// ---------------------------------------------------------------------------
// Reduce the 8 per-block partials (fixed order), add bias, squash per (b,j).
// ow_mode: 0=none, 1=set g_ow=out, 2=g_ow+=out. final_out: write d_out.
// ---------------------------------------------------------------------------
__global__ void __launch_bounds__(256)
reduce_squash(const float* __restrict__ bias, float* __restrict__ dout,
              int ow_mode, int final_out)
{
    const int b = blockIdx.x;
    const int t = threadIdx.x;  // float4 position; j = t>>2

    const float4* pp = reinterpret_cast<const float4*>(g_partials)
        + (size_t)b * SLICES * 256;
    float4 s = make_float4(0.f, 0.f, 0.f, 0.f);
#pragma unroll
    for (int s2 = 0; s2 < SLICES; s2++) {
        float4 v = pp[s2 * 256 + t];   // L2-resident, 8 independent loads
        s.x += v.x; s.y += v.y; s.z += v.z; s.w += v.w;
    }
    float4 bb = reinterpret_cast<const float4*>(bias)[t];
    s.x += bb.x; s.y += bb.y; s.z += bb.z; s.w += bb.w;

    // squash over d=16: norm^2 across the 4 threads sharing j
    float n2 = s.x * s.x + s.y * s.y + s.z * s.z + s.w * s.w;
    n2 += __shfl_xor_sync(0xffffffffu, n2, 1);
    n2 += __shfl_xor_sync(0xffffffffu, n2, 2);
    float scale = n2 / ((1.0f + n2) * sqrtf(n2 + 1e-7f));

    float4 o = make_float4(s.x * scale, s.y * scale, s.z * scale, s.w * scale);

    if (final_out) {
        reinterpret_cast<float4*>(dout)[b * 256 + t] = o;
    }
    if (ow_mode == 1) {
        reinterpret_cast<float4*>(g_ow)[b * 256 + t] = o;
    } else if (ow_mode == 2) {
        float4 c = reinterpret_cast<const float4*>(g_ow)[b * 256 + t];
        c.x += o.x; c.y += o.y; c.z += o.z; c.w += o.w;
        reinterpret_cast<float4*>(g_ow)[b * 256 + t] = c;
    }
}

extern "C" void kernel_launch(void* const* d_in, const int* in_sizes, int n_in,
                              void* d_out, int out_size)
{
    const float* x    = (const float*)d_in[0];   // [32, 2048, 64, 16]
    const float* bias = (const float*)d_in[1];   // [64, 16]
    float* out = (float*)d_out;                  // [32, 64, 16]

    (void)in_sizes; (void)n_in; (void)out_size;

    dim3 gp(NB * SLICES), bp(256);
    dim3 gr(NB), br(256);

    // Round 0: uniform weights (softmax of zero priors = 1/64)
    route_pass<<<gp, bp>>>(x, 1);
    reduce_squash<<<gr, br>>>(bias, out, /*ow_mode=*/1, /*final=*/0);  // g_ow = out0

    // Round 1: weights from softmax(dot(x, out0))
    route_pass<<<gp, bp>>>(x, 0);
    reduce_squash<<<gr, br>>>(bias, out, /*ow_mode=*/2, /*final=*/0);  // g_ow = out0+out1

    // Round 2: weights from softmax(dot(x, out0+out1)) -- linearity of priors
    route_pass<<<gp, bp>>>(x, 0);
    reduce_squash<<<gr, br>>>(bias, out, /*ow_mode=*/0, /*final=*/1);
}